// round 15
// baseline (speedup 1.0000x reference)
#include <cuda_runtime.h>
#include <cuda_bf16.h>

// ---------------------------------------------------------------------------
// Sequential logistic-regression SGD via blocked recurrence + overlap.
//   chain:  z_s = b_s - sum_{u<s} c_u G_k[u,s],  c_u = LR*(sigmoid(z_u)-y_u)
//   b^(k+1) = X_{k+1} theta_{k-1} - CG_k^T c^(k)
// Warp roles in seq_kernel (one block, 19 warps, 608 thr):
//   wid 0..15  engine: deferred theta update + p-matvec + b-finalize
//   wid 16,17  helpers: propagate c to future z's (smem zs), stage A blocks
//   wid 18     chain: scalar windowed sigmoid recurrence (highest priority)
// ---------------------------------------------------------------------------

#define F        1024
#define NTRAIN   32768
#define B        256
#define NCH      (NTRAIN / B)     // 128
#define EPOCHS   2
#define ITERS    (NCH * EPOCHS)   // 256
#define LR       0.01f
#define NT       608

__device__ float gfull_glob[(size_t)NCH * B * B + 4096];  // G[k][u][s], row-major
__device__ float cgt_glob[(size_t)NCH * B * B];           // CGT[j][s][u]

// ---------------------------------------------------------------------------
// Merged precompute: bx < 1280 -> within-chunk Gram (10 tiles/chunk)
//                    bx >= 1280 -> cross-Gram (16 tiles/pair)
// 64x64 tiles, 256 threads, 4x4 micro-tile, K-tile 16.
// ---------------------------------------------------------------------------
#define TDIM  64
#define KTILE 16
#define APAD  68

__constant__ int c_ti[10] = {0,0,0,0,1,1,1,2,2,3};
__constant__ int c_tj[10] = {0,1,2,3,1,2,3,2,3,3};

__global__ __launch_bounds__(256) void precompute_kernel(const float* __restrict__ X)
{
    __shared__ __align__(16) float As[KTILE][APAD];
    __shared__ __align__(16) float Bs[KTILE][APAD];

    const int bx = blockIdx.x;
    int rowA, rowB;           // A rows index the OUTPUT-row dim of the store
    int k, ti, tj;
    bool is_gram;
    if (bx < NCH * 10) {
        is_gram = true;
        k  = bx / 10;
        int t = bx - k * 10;
        ti = c_ti[t]; tj = c_tj[t];
        rowA = k * B + ti * TDIM;            // u rows
        rowB = k * B + tj * TDIM;            // s rows
    } else {
        is_gram = false;
        int b2 = bx - NCH * 10;
        k  = b2 >> 4;
        int t = b2 & 15;
        ti = t >> 2; tj = t & 3;
        rowA = (((k + 1) & 127) << 8) + ti * TDIM;  // s rows (next chunk)
        rowB = (k << 8) + tj * TDIM;                // u rows (chunk k)
    }

    const int tid = threadIdx.x;
    const int kl  = tid & 15;
    const int m0  = tid >> 4;
    const int tx  = tid & 15;
    const int ty  = tid >> 4;

    float acc[4][4];
#pragma unroll
    for (int i = 0; i < 4; i++)
#pragma unroll
        for (int j = 0; j < 4; j++) acc[i][j] = 0.f;

    for (int kk = 0; kk < F; kk += KTILE) {
#pragma unroll
        for (int mm = 0; mm < 4; mm++) {
            int m = m0 + 16 * mm;
            As[kl][m] = X[(size_t)(rowA + m) * F + kk + kl];
            Bs[kl][m] = X[(size_t)(rowB + m) * F + kk + kl];
        }
        __syncthreads();
#pragma unroll
        for (int kq = 0; kq < KTILE; kq++) {
            float4 a4 = *(const float4*)&As[kq][4 * ty];
            float4 b4 = *(const float4*)&Bs[kq][4 * tx];
            acc[0][0] += a4.x * b4.x; acc[0][1] += a4.x * b4.y; acc[0][2] += a4.x * b4.z; acc[0][3] += a4.x * b4.w;
            acc[1][0] += a4.y * b4.x; acc[1][1] += a4.y * b4.y; acc[1][2] += a4.y * b4.z; acc[1][3] += a4.y * b4.w;
            acc[2][0] += a4.z * b4.x; acc[2][1] += a4.z * b4.y; acc[2][2] += a4.z * b4.z; acc[2][3] += a4.z * b4.w;
            acc[3][0] += a4.w * b4.x; acc[3][1] += a4.w * b4.y; acc[3][2] += a4.w * b4.z; acc[3][3] += a4.w * b4.w;
        }
        __syncthreads();
    }

    if (is_gram) {
        float* gd = gfull_glob + ((size_t)k << 16);
#pragma unroll
        for (int ii = 0; ii < 4; ii++) {
            int u = ti * TDIM + 4 * ty + ii;
#pragma unroll
            for (int jj = 0; jj < 4; jj++) {
                int s = tj * TDIM + 4 * tx + jj;
                gd[(u << 8) + s] = acc[ii][jj];
            }
        }
    } else {
        float* cd = cgt_glob + ((size_t)k << 16);
#pragma unroll
        for (int ii = 0; ii < 4; ii++) {
            int s = ti * TDIM + 4 * ty + ii;
#pragma unroll
            for (int jj = 0; jj < 4; jj++) {
                int u = tj * TDIM + 4 * tx + jj;
                cd[((size_t)s << 8) + u] = acc[ii][jj];
            }
        }
    }
}

// ---------------------------------------------------------------------------
__global__ __launch_bounds__(NT, 1) void seq_kernel(
    const float* __restrict__ X,
    const float* __restrict__ label,
    const float* __restrict__ theta0,
    float* __restrict__ out)
{
    __shared__ __align__(16) float ths[F];
    __shared__ __align__(16) float zs[B];        // working z / incoming b
    __shared__ __align__(16) float ps[B];
    __shared__ __align__(16) float csb[2][B];
    __shared__ __align__(16) float ysb[2][B];
    __shared__ __align__(16) float abuf[2][64];  // staged 8x8 in-window G block

    const int tid  = threadIdx.x;
    const int lane = tid & 31;
    const int wid  = tid >> 5;

    ths[tid] = theta0[tid];
    if (tid + NT < F) ths[tid + NT] = theta0[tid + NT];
    __syncthreads();

    // ---- prologue: z(b0) = X_0 . theta_init ----
    {
        const float4* th4 = (const float4*)ths;
#pragma unroll 1
        for (int j2 = 0; j2 < 14; j2++) {
            int s = wid + 19 * j2;
            if (s < B) {
                const float4* xr = (const float4*)(X + (size_t)s * F);
                float acc = 0.f;
#pragma unroll
                for (int t = 0; t < 8; t++) {
                    float4 xv = xr[lane + 32 * t];
                    float4 tv = th4[lane + 32 * t];
                    acc += xv.x * tv.x + xv.y * tv.y + xv.z * tv.z + xv.w * tv.w;
                }
#pragma unroll
                for (int o = 16; o; o >>= 1)
                    acc += __shfl_down_sync(0xffffffffu, acc, o);
                if (lane == 0) zs[s] = acc;
            }
        }
        if (tid < B) ysb[0][tid] = LR * label[tid];
    }
    __syncthreads();

    for (int it = 0; it < ITERS; it++) {
        const int k = it & 127;

        if (wid == 18) {
            // ================= chain warp (scalar, windowed) =================
            const float* yb = ysb[it & 1];
            float*       cw = csb[it & 1];

            asm volatile("bar.sync 2, 96;" ::: "memory");   // barB_0 (A_0 staged)
#pragma unroll 1
            for (int w = 0; w < 32; w++) {
                // load z, y for this window; A block from smem stage
                float4 z0 = *(const float4*)&zs[w * 8];
                float4 z1 = *(const float4*)&zs[w * 8 + 4];
                float4 y0 = *(const float4*)&yb[w * 8];
                float4 y1 = *(const float4*)&yb[w * 8 + 4];
                const float4* ab4 = (const float4*)abuf[w & 1];
                float A[7][8];
#pragma unroll
                for (int i = 0; i < 7; i++) {
                    float4 lo = ab4[2 * i], hi = ab4[2 * i + 1];
                    A[i][0] = lo.x; A[i][1] = lo.y; A[i][2] = lo.z; A[i][3] = lo.w;
                    A[i][4] = hi.x; A[i][5] = hi.y; A[i][6] = hi.z; A[i][7] = hi.w;
                }
                float z[8]  = {z0.x, z0.y, z0.z, z0.w, z1.x, z1.y, z1.z, z1.w};
                float yv[8] = {y0.x, y0.y, y0.z, y0.w, y1.x, y1.y, y1.z, y1.w};
                float c[8];
#pragma unroll
                for (int q = 0; q < 8; q++) {
                    float nz = z[q] * -1.44269504089f;
                    float e;  asm("ex2.approx.f32 %0, %1;" : "=f"(e) : "f"(nz));
                    float d = e + 1.0f;
                    float r;  asm("rcp.approx.f32 %0, %1;" : "=f"(r) : "f"(d));
                    float cq = __fmaf_rn(LR, r, -yv[q]);
                    c[q] = cq;
                    if (q < 7) {
#pragma unroll
                        for (int j = q + 1; j < 8; j++)
                            z[j] = __fmaf_rn(-cq, A[q][j], z[j]);
                    }
                }
                *(float4*)&cw[w * 8]     = make_float4(c[0], c[1], c[2], c[3]);
                *(float4*)&cw[w * 8 + 4] = make_float4(c[4], c[5], c[6], c[7]);
                if (w < 31) {
                    asm volatile("bar.sync 2, 96;" ::: "memory");  // barA_{w+1}
                    asm volatile("bar.sync 2, 96;" ::: "memory");  // barB_{w+1}
                }
            }
        } else if (wid >= 16) {
            // ================= helper warps (wid 16,17) =================
            const int    hl = tid - 512;     // 0..63
            const float* gf = gfull_glob + ((size_t)k << 16);
            const float* cw = csb[it & 1];

            // stage A_0 for this chunk (warp 17 lanes 0..15)
            if (hl >= 32 && hl < 48) {
                int i = hl - 32, q = i >> 1, h = i & 1;
                *(float4*)&abuf[0][q * 8 + h * 4] =
                    *(const float4*)&gf[(q << 8) + h * 4];
            }
            asm volatile("bar.sync 2, 96;" ::: "memory");   // barB_0
            float gq[8];
#pragma unroll 1
            for (int w = 0; w < 31; w++) {
                // slow: apply c_{w-1} to zs[s >= (w+1)*8]  (runs under chain w)
                if (w >= 1) {
                    float4 c0 = *(const float4*)&cw[(w - 1) * 8];
                    float4 c1 = *(const float4*)&cw[(w - 1) * 8 + 4];
                    const float* g0 = gf + (((w - 1) * 8) << 8);
#pragma unroll 1
                    for (int s = (w + 1) * 8 + hl; s < B; s += 64) {
                        float zv = zs[s];
                        zv = __fmaf_rn(-c0.x, g0[s],           zv);
                        zv = __fmaf_rn(-c0.y, g0[256 + s],     zv);
                        zv = __fmaf_rn(-c0.z, g0[512 + s],     zv);
                        zv = __fmaf_rn(-c0.w, g0[768 + s],     zv);
                        zv = __fmaf_rn(-c1.x, g0[1024 + s],    zv);
                        zv = __fmaf_rn(-c1.y, g0[1280 + s],    zv);
                        zv = __fmaf_rn(-c1.z, g0[1536 + s],    zv);
                        zv = __fmaf_rn(-c1.w, g0[1792 + s],    zv);
                        zs[s] = zv;
                    }
                }
                // stage A_{w+1}
                if (hl >= 32 && hl < 48) {
                    int i = hl - 32, q = i >> 1, h = i & 1;
                    int wp = w + 1;
                    *(float4*)&abuf[wp & 1][q * 8 + h * 4] =
                        *(const float4*)&gf[((wp * 8 + q) << 8) + wp * 8 + h * 4];
                }
                // prefetch G for fast phase: rows w*8+q, col (w+1)*8 + hl
                if (hl < 8) {
#pragma unroll
                    for (int q = 0; q < 8; q++)
                        gq[q] = gf[((w * 8 + q) << 8) + (w + 1) * 8 + hl];
                }
                asm volatile("bar.sync 2, 96;" ::: "memory");  // barA_{w+1}
                // fast: apply c_w to zs[(w+1)*8 .. +7]
                if (hl < 8) {
                    float4 c0 = *(const float4*)&cw[w * 8];
                    float4 c1 = *(const float4*)&cw[w * 8 + 4];
                    int s = (w + 1) * 8 + hl;
                    float zv = zs[s];
                    zv = __fmaf_rn(-c0.x, gq[0], zv);
                    zv = __fmaf_rn(-c0.y, gq[1], zv);
                    zv = __fmaf_rn(-c0.z, gq[2], zv);
                    zv = __fmaf_rn(-c0.w, gq[3], zv);
                    zv = __fmaf_rn(-c1.x, gq[4], zv);
                    zv = __fmaf_rn(-c1.y, gq[5], zv);
                    zv = __fmaf_rn(-c1.z, gq[6], zv);
                    zv = __fmaf_rn(-c1.w, gq[7], zv);
                    zs[s] = zv;
                }
                asm volatile("bar.sync 2, 96;" ::: "memory");  // barB_{w+1}
            }
        } else {
            // ================= engine (warps 0..15) =================
            const int et = tid;          // 0..511
            const int ew = wid;          // 0..15

            // deferred theta update for chunk (it-1): theta -= X^T c_prev
            if (it > 0) {
                const float*  cp  = csb[(it - 1) & 1];
                const float*  xb  = X + (((size_t)((it - 1) & 127)) << 8) * F;
                float2*       th2 = (float2*)ths;
                float2 tv = th2[et];
#pragma unroll 4
                for (int s = 0; s < B; s++) {
                    float c = cp[s];
                    float2 xv = ((const float2*)(xb + (size_t)s * F))[et];
                    tv.x = __fmaf_rn(-c, xv.x, tv.x);
                    tv.y = __fmaf_rn(-c, xv.y, tv.y);
                }
                th2[et] = tv;
            }
            asm volatile("bar.sync 1, 512;" ::: "memory");

            // p = X_{(it+1)&127} . theta  (theta == theta_{it-1})
            {
                const int kn = (it + 1) & 127;
                const float*  xb  = X + (((size_t)kn) << 8) * F;
                const float4* th4 = (const float4*)ths;
#pragma unroll 1
                for (int q = 0; q < 16; q++) {
                    int s = ew * 16 + q;
                    const float4* xr = (const float4*)(xb + (size_t)s * F);
                    float acc = 0.f;
#pragma unroll
                    for (int t = 0; t < 8; t++) {
                        float4 xv = xr[lane + 32 * t];
                        float4 tv = th4[lane + 32 * t];
                        acc += xv.x * tv.x + xv.y * tv.y + xv.z * tv.z + xv.w * tv.w;
                    }
#pragma unroll
                    for (int o = 16; o; o >>= 1)
                        acc += __shfl_down_sync(0xffffffffu, acc, o);
                    if (lane == 0) ps[s] = acc;
                }
                if (et < B)
                    ysb[(it + 1) & 1][et] = LR * label[((size_t)kn << 8) + et];
            }
        }
        __syncthreads();

        // ---- b-finalize: zs = ps - CG_k^T c  (engine warps, skip last) ----
        if (it < ITERS - 1 && wid < 16) {
            const float4* cc4 = (const float4*)csb[it & 1];
            const float*  cg  = cgt_glob + ((size_t)k << 16);
#pragma unroll 1
            for (int j2 = 0; j2 < 16; j2++) {
                int s = wid + 16 * j2;
                const float4* row4 = (const float4*)(cg + ((size_t)s << 8));
                float acc = 0.f;
#pragma unroll
                for (int t = 0; t < 2; t++) {
                    float4 cv = cc4[lane + 32 * t];
                    float4 rv = row4[lane + 32 * t];
                    acc += cv.x * rv.x + cv.y * rv.y + cv.z * rv.z + cv.w * rv.w;
                }
#pragma unroll
                for (int o = 16; o; o >>= 1)
                    acc += __shfl_down_sync(0xffffffffu, acc, o);
                if (lane == 0) zs[s] = ps[s] - acc;
            }
        }
        __syncthreads();
    }

    // ---- final deferred theta update (chunk 127, c^(255)) + output ----
    {
        const float* cp = csb[(ITERS - 1) & 1];
        const float* xb = X + (((size_t)127) << 8) * F;
        const bool hi = (tid + NT) < F;
        float t0 = ths[tid];
        float t1 = hi ? ths[tid + NT] : 0.f;
#pragma unroll 4
        for (int s = 0; s < B; s++) {
            float c = cp[s];
            const float* xr = xb + (size_t)s * F;
            t0 = __fmaf_rn(-c, xr[tid], t0);
            if (hi) t1 = __fmaf_rn(-c, xr[tid + NT], t1);
        }
        out[tid] = t0;
        if (hi) out[tid + NT] = t1;
    }
}

// ---------------------------------------------------------------------------
extern "C" void kernel_launch(void* const* d_in, const int* in_sizes, int n_in,
                              void* d_out, int out_size)
{
    const float* data  = (const float*)d_in[0];   // [32768, 1024] f32
    const float* label = (const float*)d_in[1];   // [32768] f32
    const float* theta = (const float*)d_in[2];   // [1024] f32
    float*       out   = (float*)d_out;           // [1024] f32

    precompute_kernel<<<NCH * 10 + NCH * 16, 256>>>(data);
    seq_kernel<<<1, NT>>>(data, label, theta, out);
}

// round 16
// speedup vs baseline: 1.0055x; 1.0055x over previous
#include <cuda_runtime.h>
#include <cuda_bf16.h>

// ---------------------------------------------------------------------------
// Sequential logistic-regression SGD via blocked recurrence + overlap.
//   chain:  z_s = b_s - sum_{u<s} c_u G_k[u,s],  c_u = LR*(sigmoid(z_u)-y_u)
//   b^(k+1) = X_{k+1} theta_{k-1} - CG_k^T c^(k)
// Warp roles in seq_kernel (one block, 19 warps, 608 thr):
//   wid 0..15  engine: deferred theta update + p-matvec + b-finalize
//   wid 16,17  helpers: propagate c to future z's (smem zs), stage A blocks
//   wid 18     chain: scalar windowed sigmoid recurrence (highest priority)
// ---------------------------------------------------------------------------

#define F        1024
#define NTRAIN   32768
#define B        256
#define NCH      (NTRAIN / B)     // 128
#define EPOCHS   2
#define ITERS    (NCH * EPOCHS)   // 256
#define LR       0.01f
#define NT       608

__device__ float gfull_glob[(size_t)NCH * B * B + 4096];  // G[k][u][s], row-major
__device__ float cgt_glob[(size_t)NCH * B * B];           // CGT[j][s][u]

// ---------------------------------------------------------------------------
// Merged precompute: bx < 1280 -> within-chunk Gram (10 tiles/chunk)
//                    bx >= 1280 -> cross-Gram (16 tiles/pair)
// 64x64 tiles, 256 threads, 4x4 micro-tile, K-tile 16.
// ---------------------------------------------------------------------------
#define TDIM  64
#define KTILE 16
#define APAD  68

__constant__ int c_ti[10] = {0,0,0,0,1,1,1,2,2,3};
__constant__ int c_tj[10] = {0,1,2,3,1,2,3,2,3,3};

__global__ __launch_bounds__(256) void precompute_kernel(const float* __restrict__ X)
{
    __shared__ __align__(16) float As[KTILE][APAD];
    __shared__ __align__(16) float Bs[KTILE][APAD];

    const int bx = blockIdx.x;
    int rowA, rowB;           // A rows index the OUTPUT-row dim of the store
    int k, ti, tj;
    bool is_gram;
    if (bx < NCH * 10) {
        is_gram = true;
        k  = bx / 10;
        int t = bx - k * 10;
        ti = c_ti[t]; tj = c_tj[t];
        rowA = k * B + ti * TDIM;            // u rows
        rowB = k * B + tj * TDIM;            // s rows
    } else {
        is_gram = false;
        int b2 = bx - NCH * 10;
        k  = b2 >> 4;
        int t = b2 & 15;
        ti = t >> 2; tj = t & 3;
        rowA = (((k + 1) & 127) << 8) + ti * TDIM;  // s rows (next chunk)
        rowB = (k << 8) + tj * TDIM;                // u rows (chunk k)
    }

    const int tid = threadIdx.x;
    const int kl  = tid & 15;
    const int m0  = tid >> 4;
    const int tx  = tid & 15;
    const int ty  = tid >> 4;

    float acc[4][4];
#pragma unroll
    for (int i = 0; i < 4; i++)
#pragma unroll
        for (int j = 0; j < 4; j++) acc[i][j] = 0.f;

    for (int kk = 0; kk < F; kk += KTILE) {
#pragma unroll
        for (int mm = 0; mm < 4; mm++) {
            int m = m0 + 16 * mm;
            As[kl][m] = X[(size_t)(rowA + m) * F + kk + kl];
            Bs[kl][m] = X[(size_t)(rowB + m) * F + kk + kl];
        }
        __syncthreads();
#pragma unroll
        for (int kq = 0; kq < KTILE; kq++) {
            float4 a4 = *(const float4*)&As[kq][4 * ty];
            float4 b4 = *(const float4*)&Bs[kq][4 * tx];
            acc[0][0] += a4.x * b4.x; acc[0][1] += a4.x * b4.y; acc[0][2] += a4.x * b4.z; acc[0][3] += a4.x * b4.w;
            acc[1][0] += a4.y * b4.x; acc[1][1] += a4.y * b4.y; acc[1][2] += a4.y * b4.z; acc[1][3] += a4.y * b4.w;
            acc[2][0] += a4.z * b4.x; acc[2][1] += a4.z * b4.y; acc[2][2] += a4.z * b4.z; acc[2][3] += a4.z * b4.w;
            acc[3][0] += a4.w * b4.x; acc[3][1] += a4.w * b4.y; acc[3][2] += a4.w * b4.z; acc[3][3] += a4.w * b4.w;
        }
        __syncthreads();
    }

    if (is_gram) {
        float* gd = gfull_glob + ((size_t)k << 16);
#pragma unroll
        for (int ii = 0; ii < 4; ii++) {
            int u = ti * TDIM + 4 * ty + ii;
#pragma unroll
            for (int jj = 0; jj < 4; jj++) {
                int s = tj * TDIM + 4 * tx + jj;
                gd[(u << 8) + s] = acc[ii][jj];
            }
        }
    } else {
        float* cd = cgt_glob + ((size_t)k << 16);
#pragma unroll
        for (int ii = 0; ii < 4; ii++) {
            int s = ti * TDIM + 4 * ty + ii;
#pragma unroll
            for (int jj = 0; jj < 4; jj++) {
                int u = tj * TDIM + 4 * tx + jj;
                cd[((size_t)s << 8) + u] = acc[ii][jj];
            }
        }
    }
}

// ---------------------------------------------------------------------------
__global__ __launch_bounds__(NT, 1) void seq_kernel(
    const float* __restrict__ X,
    const float* __restrict__ label,
    const float* __restrict__ theta0,
    float* __restrict__ out)
{
    __shared__ __align__(16) float ths[F];
    __shared__ __align__(16) float zs[B];        // working z / incoming b
    __shared__ __align__(16) float ps[B];
    __shared__ __align__(16) float csb[2][B];
    __shared__ __align__(16) float ysb[2][B];
    __shared__ __align__(16) float abuf[2][64];  // staged 8x8 in-window G block

    const int tid  = threadIdx.x;
    const int lane = tid & 31;
    const int wid  = tid >> 5;

    ths[tid] = theta0[tid];
    if (tid + NT < F) ths[tid + NT] = theta0[tid + NT];
    __syncthreads();

    // ---- prologue: z(b0) = X_0 . theta_init ----
    {
        const float4* th4 = (const float4*)ths;
#pragma unroll 1
        for (int j2 = 0; j2 < 14; j2++) {
            int s = wid + 19 * j2;
            if (s < B) {
                const float4* xr = (const float4*)(X + (size_t)s * F);
                float acc = 0.f;
#pragma unroll
                for (int t = 0; t < 8; t++) {
                    float4 xv = xr[lane + 32 * t];
                    float4 tv = th4[lane + 32 * t];
                    acc += xv.x * tv.x + xv.y * tv.y + xv.z * tv.z + xv.w * tv.w;
                }
#pragma unroll
                for (int o = 16; o; o >>= 1)
                    acc += __shfl_down_sync(0xffffffffu, acc, o);
                if (lane == 0) zs[s] = acc;
            }
        }
        if (tid < B) ysb[0][tid] = LR * label[tid];
    }
    __syncthreads();

    for (int it = 0; it < ITERS; it++) {
        const int k = it & 127;

        if (wid == 18) {
            // ================= chain warp (scalar, windowed) =================
            const float* yb = ysb[it & 1];
            float*       cw = csb[it & 1];

            asm volatile("bar.sync 2, 96;" ::: "memory");   // barB_0 (A_0 staged)
#pragma unroll 1
            for (int w = 0; w < 32; w++) {
                // load z, y for this window; A block from smem stage
                float4 z0 = *(const float4*)&zs[w * 8];
                float4 z1 = *(const float4*)&zs[w * 8 + 4];
                float4 y0 = *(const float4*)&yb[w * 8];
                float4 y1 = *(const float4*)&yb[w * 8 + 4];
                const float4* ab4 = (const float4*)abuf[w & 1];
                float A[7][8];
#pragma unroll
                for (int i = 0; i < 7; i++) {
                    float4 lo = ab4[2 * i], hi = ab4[2 * i + 1];
                    A[i][0] = lo.x; A[i][1] = lo.y; A[i][2] = lo.z; A[i][3] = lo.w;
                    A[i][4] = hi.x; A[i][5] = hi.y; A[i][6] = hi.z; A[i][7] = hi.w;
                }
                float z[8]  = {z0.x, z0.y, z0.z, z0.w, z1.x, z1.y, z1.z, z1.w};
                float yv[8] = {y0.x, y0.y, y0.z, y0.w, y1.x, y1.y, y1.z, y1.w};
                float c[8];
#pragma unroll
                for (int q = 0; q < 8; q++) {
                    float nz = z[q] * -1.44269504089f;
                    float e;  asm("ex2.approx.f32 %0, %1;" : "=f"(e) : "f"(nz));
                    float d = e + 1.0f;
                    float r;  asm("rcp.approx.f32 %0, %1;" : "=f"(r) : "f"(d));
                    float cq = __fmaf_rn(LR, r, -yv[q]);
                    c[q] = cq;
                    if (q < 7) {
#pragma unroll
                        for (int j = q + 1; j < 8; j++)
                            z[j] = __fmaf_rn(-cq, A[q][j], z[j]);
                    }
                }
                *(float4*)&cw[w * 8]     = make_float4(c[0], c[1], c[2], c[3]);
                *(float4*)&cw[w * 8 + 4] = make_float4(c[4], c[5], c[6], c[7]);
                if (w < 31) {
                    asm volatile("bar.sync 2, 96;" ::: "memory");  // barA_{w+1}
                    asm volatile("bar.sync 2, 96;" ::: "memory");  // barB_{w+1}
                }
            }
        } else if (wid >= 16) {
            // ================= helper warps (wid 16,17) =================
            const int    hl = tid - 512;     // 0..63
            const float* gf = gfull_glob + ((size_t)k << 16);
            const float* cw = csb[it & 1];

            // stage A_0 for this chunk (warp 17 lanes 0..15)
            if (hl >= 32 && hl < 48) {
                int i = hl - 32, q = i >> 1, h = i & 1;
                *(float4*)&abuf[0][q * 8 + h * 4] =
                    *(const float4*)&gf[(q << 8) + h * 4];
            }
            asm volatile("bar.sync 2, 96;" ::: "memory");   // barB_0
            float gq[8];
#pragma unroll 1
            for (int w = 0; w < 31; w++) {
                // slow: apply c_{w-1} to zs[s >= (w+1)*8]  (runs under chain w)
                if (w >= 1) {
                    float4 c0 = *(const float4*)&cw[(w - 1) * 8];
                    float4 c1 = *(const float4*)&cw[(w - 1) * 8 + 4];
                    const float* g0 = gf + (((w - 1) * 8) << 8);
#pragma unroll 1
                    for (int s = (w + 1) * 8 + hl; s < B; s += 64) {
                        float zv = zs[s];
                        zv = __fmaf_rn(-c0.x, g0[s],           zv);
                        zv = __fmaf_rn(-c0.y, g0[256 + s],     zv);
                        zv = __fmaf_rn(-c0.z, g0[512 + s],     zv);
                        zv = __fmaf_rn(-c0.w, g0[768 + s],     zv);
                        zv = __fmaf_rn(-c1.x, g0[1024 + s],    zv);
                        zv = __fmaf_rn(-c1.y, g0[1280 + s],    zv);
                        zv = __fmaf_rn(-c1.z, g0[1536 + s],    zv);
                        zv = __fmaf_rn(-c1.w, g0[1792 + s],    zv);
                        zs[s] = zv;
                    }
                }
                // stage A_{w+1}
                if (hl >= 32 && hl < 48) {
                    int i = hl - 32, q = i >> 1, h = i & 1;
                    int wp = w + 1;
                    *(float4*)&abuf[wp & 1][q * 8 + h * 4] =
                        *(const float4*)&gf[((wp * 8 + q) << 8) + wp * 8 + h * 4];
                }
                // prefetch G for fast phase: rows w*8+q, col (w+1)*8 + hl
                if (hl < 8) {
#pragma unroll
                    for (int q = 0; q < 8; q++)
                        gq[q] = gf[((w * 8 + q) << 8) + (w + 1) * 8 + hl];
                }
                asm volatile("bar.sync 2, 96;" ::: "memory");  // barA_{w+1}
                // fast: apply c_w to zs[(w+1)*8 .. +7]
                if (hl < 8) {
                    float4 c0 = *(const float4*)&cw[w * 8];
                    float4 c1 = *(const float4*)&cw[w * 8 + 4];
                    int s = (w + 1) * 8 + hl;
                    float zv = zs[s];
                    zv = __fmaf_rn(-c0.x, gq[0], zv);
                    zv = __fmaf_rn(-c0.y, gq[1], zv);
                    zv = __fmaf_rn(-c0.z, gq[2], zv);
                    zv = __fmaf_rn(-c0.w, gq[3], zv);
                    zv = __fmaf_rn(-c1.x, gq[4], zv);
                    zv = __fmaf_rn(-c1.y, gq[5], zv);
                    zv = __fmaf_rn(-c1.z, gq[6], zv);
                    zv = __fmaf_rn(-c1.w, gq[7], zv);
                    zs[s] = zv;
                }
                asm volatile("bar.sync 2, 96;" ::: "memory");  // barB_{w+1}
            }
        } else {
            // ================= engine (warps 0..15) =================
            const int et = tid;          // 0..511
            const int ew = wid;          // 0..15

            // deferred theta update for chunk (it-1): theta -= X^T c_prev
            if (it > 0) {
                const float*  cp  = csb[(it - 1) & 1];
                const float*  xb  = X + (((size_t)((it - 1) & 127)) << 8) * F;
                float2*       th2 = (float2*)ths;
                float2 tv = th2[et];
#pragma unroll 4
                for (int s = 0; s < B; s++) {
                    float c = cp[s];
                    float2 xv = ((const float2*)(xb + (size_t)s * F))[et];
                    tv.x = __fmaf_rn(-c, xv.x, tv.x);
                    tv.y = __fmaf_rn(-c, xv.y, tv.y);
                }
                th2[et] = tv;
            }
            asm volatile("bar.sync 1, 512;" ::: "memory");

            // p = X_{(it+1)&127} . theta  (theta == theta_{it-1})
            {
                const int kn = (it + 1) & 127;
                const float*  xb  = X + (((size_t)kn) << 8) * F;
                const float4* th4 = (const float4*)ths;
#pragma unroll 1
                for (int q = 0; q < 16; q++) {
                    int s = ew * 16 + q;
                    const float4* xr = (const float4*)(xb + (size_t)s * F);
                    float acc = 0.f;
#pragma unroll
                    for (int t = 0; t < 8; t++) {
                        float4 xv = xr[lane + 32 * t];
                        float4 tv = th4[lane + 32 * t];
                        acc += xv.x * tv.x + xv.y * tv.y + xv.z * tv.z + xv.w * tv.w;
                    }
#pragma unroll
                    for (int o = 16; o; o >>= 1)
                        acc += __shfl_down_sync(0xffffffffu, acc, o);
                    if (lane == 0) ps[s] = acc;
                }
                if (et < B)
                    ysb[(it + 1) & 1][et] = LR * label[((size_t)kn << 8) + et];
            }
        }
        __syncthreads();

        // ---- b-finalize: zs = ps - CG_k^T c  (engine warps, skip last) ----
        if (it < ITERS - 1 && wid < 16) {
            const float4* cc4 = (const float4*)csb[it & 1];
            const float*  cg  = cgt_glob + ((size_t)k << 16);
#pragma unroll 1
            for (int j2 = 0; j2 < 16; j2++) {
                int s = wid + 16 * j2;
                const float4* row4 = (const float4*)(cg + ((size_t)s << 8));
                float acc = 0.f;
#pragma unroll
                for (int t = 0; t < 2; t++) {
                    float4 cv = cc4[lane + 32 * t];
                    float4 rv = row4[lane + 32 * t];
                    acc += cv.x * rv.x + cv.y * rv.y + cv.z * rv.z + cv.w * rv.w;
                }
#pragma unroll
                for (int o = 16; o; o >>= 1)
                    acc += __shfl_down_sync(0xffffffffu, acc, o);
                if (lane == 0) zs[s] = ps[s] - acc;
            }
        }
        __syncthreads();
    }

    // ---- final deferred theta update (chunk 127, c^(255)) + output ----
    {
        const float* cp = csb[(ITERS - 1) & 1];
        const float* xb = X + (((size_t)127) << 8) * F;
        const bool hi = (tid + NT) < F;
        float t0 = ths[tid];
        float t1 = hi ? ths[tid + NT] : 0.f;
#pragma unroll 4
        for (int s = 0; s < B; s++) {
            float c = cp[s];
            const float* xr = xb + (size_t)s * F;
            t0 = __fmaf_rn(-c, xr[tid], t0);
            if (hi) t1 = __fmaf_rn(-c, xr[tid + NT], t1);
        }
        out[tid] = t0;
        if (hi) out[tid + NT] = t1;
    }
}

// ---------------------------------------------------------------------------
extern "C" void kernel_launch(void* const* d_in, const int* in_sizes, int n_in,
                              void* d_out, int out_size)
{
    const float* data  = (const float*)d_in[0];   // [32768, 1024] f32
    const float* label = (const float*)d_in[1];   // [32768] f32
    const float* theta = (const float*)d_in[2];   // [1024] f32
    float*       out   = (float*)d_out;           // [1024] f32

    precompute_kernel<<<NCH * 10 + NCH * 16, 256>>>(data);
    seq_kernel<<<1, NT>>>(data, label, theta, out);
}

// round 17
// speedup vs baseline: 1.0154x; 1.0099x over previous
#include <cuda_runtime.h>
#include <cuda_bf16.h>

// ---------------------------------------------------------------------------
// Sequential logistic-regression SGD via blocked recurrence + overlap.
//   chain:  z_s = b_s - sum_{u<s} c_u G_k[u,s],  c_u = LR*(sigmoid(z_u)-y_u)
//   b^(k+1) = X_{k+1} theta_{k-1} - CG_k^T c^(k)
// Warp roles in seq_kernel (one block, 19 warps, 608 thr):
//   wid 0..15  engine: deferred theta update + p-matvec + b-finalize
//   wid 16,17  helpers: propagate c to future z's (smem zs), stage A blocks
//   wid 18     chain: scalar windowed sigmoid recurrence (highest priority)
// ---------------------------------------------------------------------------

#define F        1024
#define NTRAIN   32768
#define B        256
#define NCH      (NTRAIN / B)     // 128
#define EPOCHS   2
#define ITERS    (NCH * EPOCHS)   // 256
#define LR       0.01f
#define NT       608

__device__ float gfull_glob[(size_t)NCH * B * B + 4096];  // G[k][u][s], row-major
__device__ float cgt_glob[(size_t)NCH * B * B];           // CGT[j][s][u]

// ---------------------------------------------------------------------------
// Merged precompute: bx < 1280 -> within-chunk Gram (10 tiles/chunk)
//                    bx >= 1280 -> cross-Gram (16 tiles/pair)
// 64x64 tiles, 256 threads, 4x4 micro-tile, K-tile 16.
// ---------------------------------------------------------------------------
#define TDIM  64
#define KTILE 16
#define APAD  68

__constant__ int c_ti[10] = {0,0,0,0,1,1,1,2,2,3};
__constant__ int c_tj[10] = {0,1,2,3,1,2,3,2,3,3};

__global__ __launch_bounds__(256) void precompute_kernel(const float* __restrict__ X)
{
    __shared__ __align__(16) float As[KTILE][APAD];
    __shared__ __align__(16) float Bs[KTILE][APAD];

    const int bx = blockIdx.x;
    int rowA, rowB;           // A rows index the OUTPUT-row dim of the store
    int k, ti, tj;
    bool is_gram;
    if (bx < NCH * 10) {
        is_gram = true;
        k  = bx / 10;
        int t = bx - k * 10;
        ti = c_ti[t]; tj = c_tj[t];
        rowA = k * B + ti * TDIM;            // u rows
        rowB = k * B + tj * TDIM;            // s rows
    } else {
        is_gram = false;
        int b2 = bx - NCH * 10;
        k  = b2 >> 4;
        int t = b2 & 15;
        ti = t >> 2; tj = t & 3;
        rowA = (((k + 1) & 127) << 8) + ti * TDIM;  // s rows (next chunk)
        rowB = (k << 8) + tj * TDIM;                // u rows (chunk k)
    }

    const int tid = threadIdx.x;
    const int kl  = tid & 15;
    const int m0  = tid >> 4;
    const int tx  = tid & 15;
    const int ty  = tid >> 4;

    float acc[4][4];
#pragma unroll
    for (int i = 0; i < 4; i++)
#pragma unroll
        for (int j = 0; j < 4; j++) acc[i][j] = 0.f;

    for (int kk = 0; kk < F; kk += KTILE) {
#pragma unroll
        for (int mm = 0; mm < 4; mm++) {
            int m = m0 + 16 * mm;
            As[kl][m] = X[(size_t)(rowA + m) * F + kk + kl];
            Bs[kl][m] = X[(size_t)(rowB + m) * F + kk + kl];
        }
        __syncthreads();
#pragma unroll
        for (int kq = 0; kq < KTILE; kq++) {
            float4 a4 = *(const float4*)&As[kq][4 * ty];
            float4 b4 = *(const float4*)&Bs[kq][4 * tx];
            acc[0][0] += a4.x * b4.x; acc[0][1] += a4.x * b4.y; acc[0][2] += a4.x * b4.z; acc[0][3] += a4.x * b4.w;
            acc[1][0] += a4.y * b4.x; acc[1][1] += a4.y * b4.y; acc[1][2] += a4.y * b4.z; acc[1][3] += a4.y * b4.w;
            acc[2][0] += a4.z * b4.x; acc[2][1] += a4.z * b4.y; acc[2][2] += a4.z * b4.z; acc[2][3] += a4.z * b4.w;
            acc[3][0] += a4.w * b4.x; acc[3][1] += a4.w * b4.y; acc[3][2] += a4.w * b4.z; acc[3][3] += a4.w * b4.w;
        }
        __syncthreads();
    }

    if (is_gram) {
        float* gd = gfull_glob + ((size_t)k << 16);
#pragma unroll
        for (int ii = 0; ii < 4; ii++) {
            int u = ti * TDIM + 4 * ty + ii;
#pragma unroll
            for (int jj = 0; jj < 4; jj++) {
                int s = tj * TDIM + 4 * tx + jj;
                gd[(u << 8) + s] = acc[ii][jj];
            }
        }
    } else {
        float* cd = cgt_glob + ((size_t)k << 16);
#pragma unroll
        for (int ii = 0; ii < 4; ii++) {
            int s = ti * TDIM + 4 * ty + ii;
#pragma unroll
            for (int jj = 0; jj < 4; jj++) {
                int u = tj * TDIM + 4 * tx + jj;
                cd[((size_t)s << 8) + u] = acc[ii][jj];
            }
        }
    }
}

// ---------------------------------------------------------------------------
__global__ __launch_bounds__(NT, 1) void seq_kernel(
    const float* __restrict__ X,
    const float* __restrict__ label,
    const float* __restrict__ theta0,
    float* __restrict__ out)
{
    __shared__ __align__(16) float ths[F];
    __shared__ __align__(16) float zs[B];        // working z / incoming b
    __shared__ __align__(16) float ps[B];
    __shared__ __align__(16) float csb[2][B];
    __shared__ __align__(16) float ysb[2][B];
    __shared__ __align__(16) float abuf[2][64];  // staged 8x8 in-window G block

    const int tid  = threadIdx.x;
    const int lane = tid & 31;
    const int wid  = tid >> 5;

    ths[tid] = theta0[tid];
    if (tid + NT < F) ths[tid + NT] = theta0[tid + NT];
    __syncthreads();

    // ---- prologue: z(b0) = X_0 . theta_init ----
    {
        const float4* th4 = (const float4*)ths;
#pragma unroll 1
        for (int j2 = 0; j2 < 14; j2++) {
            int s = wid + 19 * j2;
            if (s < B) {
                const float4* xr = (const float4*)(X + (size_t)s * F);
                float acc = 0.f;
#pragma unroll
                for (int t = 0; t < 8; t++) {
                    float4 xv = xr[lane + 32 * t];
                    float4 tv = th4[lane + 32 * t];
                    acc += xv.x * tv.x + xv.y * tv.y + xv.z * tv.z + xv.w * tv.w;
                }
#pragma unroll
                for (int o = 16; o; o >>= 1)
                    acc += __shfl_down_sync(0xffffffffu, acc, o);
                if (lane == 0) zs[s] = acc;
            }
        }
        if (tid < B) ysb[0][tid] = LR * label[tid];
    }
    __syncthreads();

    for (int it = 0; it < ITERS; it++) {
        const int k = it & 127;

        if (wid == 18) {
            // ================= chain warp (scalar, windowed) =================
            const float* yb = ysb[it & 1];
            float*       cw = csb[it & 1];

            asm volatile("bar.sync 2, 96;" ::: "memory");   // barB_0 (A_0 staged)
#pragma unroll 1
            for (int w = 0; w < 32; w++) {
                // load z, y for this window; A block from smem stage
                float4 z0 = *(const float4*)&zs[w * 8];
                float4 z1 = *(const float4*)&zs[w * 8 + 4];
                float4 y0 = *(const float4*)&yb[w * 8];
                float4 y1 = *(const float4*)&yb[w * 8 + 4];
                const float4* ab4 = (const float4*)abuf[w & 1];
                float A[7][8];
#pragma unroll
                for (int i = 0; i < 7; i++) {
                    float4 lo = ab4[2 * i], hi = ab4[2 * i + 1];
                    A[i][0] = lo.x; A[i][1] = lo.y; A[i][2] = lo.z; A[i][3] = lo.w;
                    A[i][4] = hi.x; A[i][5] = hi.y; A[i][6] = hi.z; A[i][7] = hi.w;
                }
                float z[8]  = {z0.x, z0.y, z0.z, z0.w, z1.x, z1.y, z1.z, z1.w};
                float yv[8] = {y0.x, y0.y, y0.z, y0.w, y1.x, y1.y, y1.z, y1.w};
                float c[8];
#pragma unroll
                for (int q = 0; q < 8; q++) {
                    float nz = z[q] * -1.44269504089f;
                    float e;  asm("ex2.approx.f32 %0, %1;" : "=f"(e) : "f"(nz));
                    float d = e + 1.0f;
                    float r;  asm("rcp.approx.f32 %0, %1;" : "=f"(r) : "f"(d));
                    float cq = __fmaf_rn(LR, r, -yv[q]);
                    c[q] = cq;
                    if (q < 7) {
#pragma unroll
                        for (int j = q + 1; j < 8; j++)
                            z[j] = __fmaf_rn(-cq, A[q][j], z[j]);
                    }
                }
                *(float4*)&cw[w * 8]     = make_float4(c[0], c[1], c[2], c[3]);
                *(float4*)&cw[w * 8 + 4] = make_float4(c[4], c[5], c[6], c[7]);
                if (w < 31) {
                    asm volatile("bar.sync 2, 96;" ::: "memory");  // barA_{w+1}
                    asm volatile("bar.sync 2, 96;" ::: "memory");  // barB_{w+1}
                }
            }
        } else if (wid >= 16) {
            // ================= helper warps (wid 16,17) =================
            const int    hl = tid - 512;     // 0..63
            const float* gf = gfull_glob + ((size_t)k << 16);
            const float* cw = csb[it & 1];

            // stage A_0 for this chunk (warp 17 lanes 0..15)
            if (hl >= 32 && hl < 48) {
                int i = hl - 32, q = i >> 1, h = i & 1;
                *(float4*)&abuf[0][q * 8 + h * 4] =
                    *(const float4*)&gf[(q << 8) + h * 4];
            }
            asm volatile("bar.sync 2, 96;" ::: "memory");   // barB_0
            float gq[8];
#pragma unroll 1
            for (int w = 0; w < 31; w++) {
                // slow: apply c_{w-1} to zs[s >= (w+1)*8]  (runs under chain w)
                if (w >= 1) {
                    float4 c0 = *(const float4*)&cw[(w - 1) * 8];
                    float4 c1 = *(const float4*)&cw[(w - 1) * 8 + 4];
                    const float* g0 = gf + (((w - 1) * 8) << 8);
#pragma unroll 1
                    for (int s = (w + 1) * 8 + hl; s < B; s += 64) {
                        float zv = zs[s];
                        zv = __fmaf_rn(-c0.x, g0[s],           zv);
                        zv = __fmaf_rn(-c0.y, g0[256 + s],     zv);
                        zv = __fmaf_rn(-c0.z, g0[512 + s],     zv);
                        zv = __fmaf_rn(-c0.w, g0[768 + s],     zv);
                        zv = __fmaf_rn(-c1.x, g0[1024 + s],    zv);
                        zv = __fmaf_rn(-c1.y, g0[1280 + s],    zv);
                        zv = __fmaf_rn(-c1.z, g0[1536 + s],    zv);
                        zv = __fmaf_rn(-c1.w, g0[1792 + s],    zv);
                        zs[s] = zv;
                    }
                }
                // stage A_{w+1}
                if (hl >= 32 && hl < 48) {
                    int i = hl - 32, q = i >> 1, h = i & 1;
                    int wp = w + 1;
                    *(float4*)&abuf[wp & 1][q * 8 + h * 4] =
                        *(const float4*)&gf[((wp * 8 + q) << 8) + wp * 8 + h * 4];
                }
                // prefetch G for fast phase: rows w*8+q, col (w+1)*8 + hl
                if (hl < 8) {
#pragma unroll
                    for (int q = 0; q < 8; q++)
                        gq[q] = gf[((w * 8 + q) << 8) + (w + 1) * 8 + hl];
                }
                asm volatile("bar.sync 2, 96;" ::: "memory");  // barA_{w+1}
                // fast: apply c_w to zs[(w+1)*8 .. +7]
                if (hl < 8) {
                    float4 c0 = *(const float4*)&cw[w * 8];
                    float4 c1 = *(const float4*)&cw[w * 8 + 4];
                    int s = (w + 1) * 8 + hl;
                    float zv = zs[s];
                    zv = __fmaf_rn(-c0.x, gq[0], zv);
                    zv = __fmaf_rn(-c0.y, gq[1], zv);
                    zv = __fmaf_rn(-c0.z, gq[2], zv);
                    zv = __fmaf_rn(-c0.w, gq[3], zv);
                    zv = __fmaf_rn(-c1.x, gq[4], zv);
                    zv = __fmaf_rn(-c1.y, gq[5], zv);
                    zv = __fmaf_rn(-c1.z, gq[6], zv);
                    zv = __fmaf_rn(-c1.w, gq[7], zv);
                    zs[s] = zv;
                }
                asm volatile("bar.sync 2, 96;" ::: "memory");  // barB_{w+1}
            }
        } else {
            // ================= engine (warps 0..15) =================
            const int et = tid;          // 0..511
            const int ew = wid;          // 0..15

            // deferred theta update for chunk (it-1): theta -= X^T c_prev
            if (it > 0) {
                const float*  cp  = csb[(it - 1) & 1];
                const float*  xb  = X + (((size_t)((it - 1) & 127)) << 8) * F;
                float2*       th2 = (float2*)ths;
                float2 tv = th2[et];
#pragma unroll 4
                for (int s = 0; s < B; s++) {
                    float c = cp[s];
                    float2 xv = ((const float2*)(xb + (size_t)s * F))[et];
                    tv.x = __fmaf_rn(-c, xv.x, tv.x);
                    tv.y = __fmaf_rn(-c, xv.y, tv.y);
                }
                th2[et] = tv;
            }
            asm volatile("bar.sync 1, 512;" ::: "memory");

            // p = X_{(it+1)&127} . theta  (theta == theta_{it-1})
            {
                const int kn = (it + 1) & 127;
                const float*  xb  = X + (((size_t)kn) << 8) * F;
                const float4* th4 = (const float4*)ths;
#pragma unroll 1
                for (int q = 0; q < 16; q++) {
                    int s = ew * 16 + q;
                    const float4* xr = (const float4*)(xb + (size_t)s * F);
                    float acc = 0.f;
#pragma unroll
                    for (int t = 0; t < 8; t++) {
                        float4 xv = xr[lane + 32 * t];
                        float4 tv = th4[lane + 32 * t];
                        acc += xv.x * tv.x + xv.y * tv.y + xv.z * tv.z + xv.w * tv.w;
                    }
#pragma unroll
                    for (int o = 16; o; o >>= 1)
                        acc += __shfl_down_sync(0xffffffffu, acc, o);
                    if (lane == 0) ps[s] = acc;
                }
                if (et < B)
                    ysb[(it + 1) & 1][et] = LR * label[((size_t)kn << 8) + et];
            }
        }
        __syncthreads();

        // ---- b-finalize: zs = ps - CG_k^T c  (engine warps, skip last) ----
        if (it < ITERS - 1 && wid < 16) {
            const float4* cc4 = (const float4*)csb[it & 1];
            const float*  cg  = cgt_glob + ((size_t)k << 16);
#pragma unroll 1
            for (int j2 = 0; j2 < 16; j2++) {
                int s = wid + 16 * j2;
                const float4* row4 = (const float4*)(cg + ((size_t)s << 8));
                float acc = 0.f;
#pragma unroll
                for (int t = 0; t < 2; t++) {
                    float4 cv = cc4[lane + 32 * t];
                    float4 rv = row4[lane + 32 * t];
                    acc += cv.x * rv.x + cv.y * rv.y + cv.z * rv.z + cv.w * rv.w;
                }
#pragma unroll
                for (int o = 16; o; o >>= 1)
                    acc += __shfl_down_sync(0xffffffffu, acc, o);
                if (lane == 0) zs[s] = ps[s] - acc;
            }
        }
        __syncthreads();
    }

    // ---- final deferred theta update (chunk 127, c^(255)) + output ----
    {
        const float* cp = csb[(ITERS - 1) & 1];
        const float* xb = X + (((size_t)127) << 8) * F;
        const bool hi = (tid + NT) < F;
        float t0 = ths[tid];
        float t1 = hi ? ths[tid + NT] : 0.f;
#pragma unroll 4
        for (int s = 0; s < B; s++) {
            float c = cp[s];
            const float* xr = xb + (size_t)s * F;
            t0 = __fmaf_rn(-c, xr[tid], t0);
            if (hi) t1 = __fmaf_rn(-c, xr[tid + NT], t1);
        }
        out[tid] = t0;
        if (hi) out[tid + NT] = t1;
    }
}

// ---------------------------------------------------------------------------
extern "C" void kernel_launch(void* const* d_in, const int* in_sizes, int n_in,
                              void* d_out, int out_size)
{
    const float* data  = (const float*)d_in[0];   // [32768, 1024] f32
    const float* label = (const float*)d_in[1];   // [32768] f32
    const float* theta = (const float*)d_in[2];   // [1024] f32
    float*       out   = (float*)d_out;           // [1024] f32

    precompute_kernel<<<NCH * 10 + NCH * 16, 256>>>(data);
    seq_kernel<<<1, NT>>>(data, label, theta, out);
}